// round 17
// baseline (speedup 1.0000x reference)
#include <cuda_runtime.h>
#include <cuda_bf16.h>
#include <stdint.h>
#include <math.h>

#define TT   4096
#define DD   1024
#define HH   512
#define EE   32
#define KTOP 4
#define CAP  2048
#define HS   1024

typedef __nv_bfloat16 bf16;

// ---------------- scratch (device globals; no allocations allowed) ----------
__device__ int   g_cnt[EE];
__device__ int   g_pid[EE * CAP];
__device__ float g_wt [EE * CAP];
__device__ float g_po [(size_t)TT * KTOP * DD];

__device__ float g_t1 [(size_t)EE * CAP * HH];   // routed x@W1
__device__ float g_t3 [(size_t)EE * CAP * HH];   // routed x@W3
__device__ float g_s1 [(size_t)TT * HS];         // shared x@Ws1
__device__ float g_s3 [(size_t)TT * HS];         // shared x@Ws3
__device__ bf16  g_hhi[(size_t)EE * CAP * HH];   // routed hidden hi/lo
__device__ bf16  g_hlo[(size_t)EE * CAP * HH];
__device__ bf16  g_shi[(size_t)TT * HS];         // shared hidden hi/lo
__device__ bf16  g_slo[(size_t)TT * HS];

// ---------------- helpers ----------------------------------------------------
__device__ __forceinline__ uint32_t smem_u32(const void* p) {
    uint32_t a;
    asm("{ .reg .u64 t; cvta.to.shared.u64 t, %1; cvt.u32.u64 %0, t; }"
        : "=r"(a) : "l"(p));
    return a;
}
__device__ __forceinline__ void ldsm4(uint32_t* r, uint32_t addr) {
    asm volatile("ldmatrix.sync.aligned.m8n8.x4.shared.b16 {%0,%1,%2,%3}, [%4];"
        : "=r"(r[0]), "=r"(r[1]), "=r"(r[2]), "=r"(r[3]) : "r"(addr));
}
__device__ __forceinline__ void ldsm4t(uint32_t* r, uint32_t addr) {
    asm volatile("ldmatrix.sync.aligned.m8n8.x4.trans.shared.b16 {%0,%1,%2,%3}, [%4];"
        : "=r"(r[0]), "=r"(r[1]), "=r"(r[2]), "=r"(r[3]) : "r"(addr));
}
__device__ __forceinline__ void mma16816(float* d, const uint32_t* a, const uint32_t* b) {
    asm volatile("mma.sync.aligned.m16n8k16.row.col.f32.bf16.bf16.f32 "
        "{%0,%1,%2,%3}, {%4,%5,%6,%7}, {%8,%9}, {%0,%1,%2,%3};"
        : "+f"(d[0]), "+f"(d[1]), "+f"(d[2]), "+f"(d[3])
        : "r"(a[0]), "r"(a[1]), "r"(a[2]), "r"(a[3]), "r"(b[0]), "r"(b[1]));
}
__device__ __forceinline__ uint32_t pk2(float a, float b) {
    union { __nv_bfloat162 v; uint32_t u; } t;
    t.v = __halves2bfloat162(__float2bfloat16_rn(a), __float2bfloat16_rn(b));
    return t.u;
}
__device__ __forceinline__ float bl(uint32_t u, int hi) {
    union { uint32_t u; __nv_bfloat162 v; } t; t.u = u;
    return hi ? __bfloat162float(__high2bfloat16(t.v))
              : __bfloat162float(__low2bfloat16(t.v));
}
__device__ __forceinline__ void split8(const float* f, uint4& h, uint4& l) {
    uint32_t hw[4], lw[4];
#pragma unroll
    for (int j = 0; j < 4; j++) {
        hw[j] = pk2(f[2*j], f[2*j+1]);
        lw[j] = pk2(f[2*j] - bl(hw[j], 0), f[2*j+1] - bl(hw[j], 1));
    }
    h = make_uint4(hw[0], hw[1], hw[2], hw[3]);
    l = make_uint4(lw[0], lw[1], lw[2], lw[3]);
}
__device__ __forceinline__ float silu_f(float a) { return a / (1.0f + expf(-a)); }

// ---------------- small kernels ----------------------------------------------
__global__ void zero_cnt_kernel() { if (threadIdx.x < EE) g_cnt[threadIdx.x] = 0; }

__global__ void gate_kernel(const float* __restrict__ x,
                            const float* __restrict__ Wg) {
    __shared__ float xs[DD];
    __shared__ float part[4][EE];
    int t = blockIdx.x;
    const float* xr = x + (size_t)t * DD;
    for (int i = threadIdx.x; i < DD / 4; i += 128)
        ((float4*)xs)[i] = ((const float4*)xr)[i];
    __syncthreads();
    int e = threadIdx.x & 31, c = threadIdx.x >> 5;
    float s = 0.f;
    for (int d = c * (DD / 4); d < (c + 1) * (DD / 4); d++)
        s += xs[d] * Wg[d * EE + e];
    part[c][e] = s;
    __syncthreads();
    if (threadIdx.x < 32) {
        float logit = part[0][e] + part[1][e] + part[2][e] + part[3][e];
        float m = logit;
        for (int o = 16; o; o >>= 1) m = fmaxf(m, __shfl_xor_sync(~0u, m, o));
        float ex = expf(logit - m);
        float sum = ex;
        for (int o = 16; o; o >>= 1) sum += __shfl_xor_sync(~0u, sum, o);
        float v = ex / sum;
        for (int k = 0; k < KTOP; k++) {
            float bv = v; int bi = e;
            for (int o = 16; o; o >>= 1) {
                float ov = __shfl_xor_sync(~0u, bv, o);
                int   oi = __shfl_xor_sync(~0u, bi, o);
                if (ov > bv || (ov == bv && oi < bi)) { bv = ov; bi = oi; }
            }
            if (e == 0) {
                int slot = atomicAdd(&g_cnt[bi], 1);
                if (slot < CAP) {
                    g_pid[bi * CAP + slot] = t * KTOP + k;
                    g_wt [bi * CAP + slot] = bv;
                }
            }
            if (e == bi) v = -1.0f;
        }
    }
}

// elementwise: h = silu(a1)*a3 -> bf16 hi/lo
__global__ void act_kernel(const float* __restrict__ a1, const float* __restrict__ a3,
                           bf16* __restrict__ ohi, bf16* __restrict__ olo) {
    size_t i = (size_t)blockIdx.x * 256 + threadIdx.x;   // float4 index
    float4 v1 = ((const float4*)a1)[i];
    float4 v3 = ((const float4*)a3)[i];
    float f[4];
    f[0] = silu_f(v1.x) * v3.x; f[1] = silu_f(v1.y) * v3.y;
    f[2] = silu_f(v1.z) * v3.z; f[3] = silu_f(v1.w) * v3.w;
    uint32_t h0 = pk2(f[0], f[1]), h1 = pk2(f[2], f[3]);
    uint32_t l0 = pk2(f[0] - bl(h0, 0), f[1] - bl(h0, 1));
    uint32_t l1 = pk2(f[2] - bl(h1, 0), f[3] - bl(h1, 1));
    ((uint2*)ohi)[i] = make_uint2(h0, h1);
    ((uint2*)olo)[i] = make_uint2(l0, l1);
}

// ---------------- generic mma.sync GEMM --------------------------------------
// C[128M x 64N] per CTA, BK=64. 8 warps, warp tile 32M x 32N.
// A operand: hi/lo bf16 in smem [m][k] 128B rows (SW128), ldmatrix non-trans.
// B operand: hi/lo bf16 in smem [k][n] 128B rows (SW128), ldmatrix trans.
// 3-term split: Ah*Bh + Ah*Bl + Al*Bh, fp32 accum.
// MODE 0: routed gemm1 (A = x gathered via g_pid, B = W[e], out fp32 e*CAP rows)
// MODE 1: shared gemm1 (A = x linear,  B = Ws, out fp32 linear rows)
// MODE 2: routed gemm2 (A = g_hhi/g_hlo at e*CAP rows, out = g_po[pid]*wt)
// MODE 3: shared gemm2 (A = g_shi/g_slo linear, out = y)
#define SM_AH 0
#define SM_AL 16384
#define SM_BH 32768
#define SM_BL 40960
#define SM_RW 49152
#define GEMM_SMEM (49152 + 512)

template<int MODE>
__global__ void __launch_bounds__(256, 2)
gemm_kernel(const float* __restrict__ Af, const bf16* __restrict__ Abh,
            const bf16* __restrict__ Abl, const float* __restrict__ Bf,
            float* __restrict__ out, int Kdim, int Ntot) {
    extern __shared__ char sm[];
    const bool ROUTED = (MODE == 0) || (MODE == 2);
    int e   = ROUTED ? blockIdx.z : 0;
    int cnt = ROUTED ? min(g_cnt[e], CAP) : TT;
    int m0  = blockIdx.y * 128; if (m0 >= cnt) return;
    int n0  = blockIdx.x * 64;
    int tid = threadIdx.x, lane = tid & 31, wid = tid >> 5;
    int wm = (wid >> 1) * 32, wn = (wid & 1) * 32;
    uint32_t smb = smem_u32(sm);
    int* rows = (int*)(sm + SM_RW);
    if (MODE == 0 && tid < 128) {
        int r = m0 + tid;
        rows[tid] = (r < cnt) ? (g_pid[e * CAP + r] >> 2) : 0;
    }
    if (MODE == 0) __syncthreads();

    const float* Bp = Bf + (ROUTED ? (size_t)e * Kdim * Ntot : (size_t)0) + n0;
    size_t abase = (MODE == 2) ? ((size_t)e * CAP + m0) * Kdim
                               : (size_t)m0 * Kdim;        // MODE 1/3 linear
    float acc[2][4][4] = {};

    for (int k0 = 0; k0 < Kdim; k0 += 64) {
        __syncthreads();
        // ---- A tile: 128 x 64 ----
        if (MODE <= 1) {
#pragma unroll
            for (int i = 0; i < 4; i++) {
                int u = tid + i * 256, m = u >> 3, c = u & 7;
                size_t row = (MODE == 0) ? (size_t)rows[m] : (size_t)(m0 + m);
                const float* s = Af + row * Kdim + k0 + c * 8;
                float f[8];
                *(float4*)(f)     = *(const float4*)(s);
                *(float4*)(f + 4) = *(const float4*)(s + 4);
                uint4 h, l; split8(f, h, l);
                int off = m * 128 + ((c * 16) ^ ((m & 7) << 4));
                *(uint4*)(sm + SM_AH + off) = h;
                *(uint4*)(sm + SM_AL + off) = l;
            }
        } else {
#pragma unroll
            for (int i = 0; i < 4; i++) {
                int u = tid + i * 256, m = u >> 3, c = u & 7;
                size_t soff = abase + (size_t)m * Kdim + k0 + c * 8;
                int off = m * 128 + ((c * 16) ^ ((m & 7) << 4));
                *(uint4*)(sm + SM_AH + off) = *(const uint4*)(Abh + soff);
                *(uint4*)(sm + SM_AL + off) = *(const uint4*)(Abl + soff);
            }
        }
        // ---- B tile: 64k x 64n, [k][n] ----
#pragma unroll
        for (int i = 0; i < 2; i++) {
            int u = tid + i * 256, kr = u >> 3, c = u & 7;
            const float* s = Bp + (size_t)(k0 + kr) * Ntot + c * 8;
            float f[8];
            *(float4*)(f)     = *(const float4*)(s);
            *(float4*)(f + 4) = *(const float4*)(s + 4);
            uint4 h, l; split8(f, h, l);
            int off = kr * 128 + ((c * 16) ^ ((kr & 7) << 4));
            *(uint4*)(sm + SM_BH + off) = h;
            *(uint4*)(sm + SM_BL + off) = l;
        }
        __syncthreads();

#pragma unroll
        for (int ks = 0; ks < 4; ks++) {
            uint32_t ah[2][4], al_[2][4];
#pragma unroll
            for (int ma = 0; ma < 2; ma++) {
                int rr = wm + ma * 16 + ((lane >> 3) & 1) * 8 + (lane & 7);
                uint32_t byte = rr * 128 + (((uint32_t)(ks * 32 + (lane >> 4) * 16)) ^ ((rr & 7) << 4));
                ldsm4(ah[ma],  smb + SM_AH + byte);
                ldsm4(al_[ma], smb + SM_AL + byte);
            }
            uint32_t bh[2][4], blo[2][4];
            {
                int krow = ks * 16 + (lane & 15);
#pragma unroll
                for (int nh = 0; nh < 2; nh++) {
                    uint32_t byte = krow * 128 +
                        (((uint32_t)((wn + nh * 16 + (lane >> 4) * 8) * 2)) ^ ((krow & 7) << 4));
                    ldsm4t(bh[nh],  smb + SM_BH + byte);
                    ldsm4t(blo[nh], smb + SM_BL + byte);
                }
            }
#pragma unroll
            for (int ma = 0; ma < 2; ma++)
#pragma unroll
            for (int ns = 0; ns < 4; ns++) {
                const uint32_t* bhp = &bh [ns >> 1][(ns & 1) * 2];
                const uint32_t* blp = &blo[ns >> 1][(ns & 1) * 2];
                mma16816(acc[ma][ns], ah[ma],  bhp);
                mma16816(acc[ma][ns], ah[ma],  blp);
                mma16816(acc[ma][ns], al_[ma], bhp);
            }
        }
    }

    // ---- epilogue ----
#pragma unroll
    for (int ma = 0; ma < 2; ma++)
#pragma unroll
    for (int half = 0; half < 2; half++) {
        int r = m0 + wm + ma * 16 + (lane >> 2) + half * 8;
        if (r >= cnt) continue;
        float w = 1.0f;
        float* dst;
        if (MODE == 0)      dst = out + ((size_t)e * CAP + r) * Ntot;
        else if (MODE == 1) dst = out + (size_t)r * Ntot;
        else if (MODE == 2) {
            int pid = g_pid[e * CAP + r];
            w = g_wt[e * CAP + r];
            dst = g_po + (size_t)pid * DD;
        } else              dst = out + (size_t)r * DD;
#pragma unroll
        for (int ns = 0; ns < 4; ns++) {
            int col = n0 + wn + (ns >> 1) * 16 + (ns & 1) * 8 + (lane & 3) * 2;
            float2 o;
            o.x = acc[ma][ns][half * 2]     * w;
            o.y = acc[ma][ns][half * 2 + 1] * w;
            *(float2*)(dst + col) = o;
        }
    }
}

// combine: y[t] += sum_k po[t*4+k]
__global__ void combine_kernel(float* __restrict__ y) {
    size_t i  = (size_t)blockIdx.x * 256 + threadIdx.x;
    size_t t  = i >> 8;
    size_t c4 = i & 255;
    float4 acc = ((float4*)y)[i];
    const float4* po4 = (const float4*)g_po;
#pragma unroll
    for (int k = 0; k < KTOP; k++) {
        float4 p = po4[(t * KTOP + k) * (DD / 4) + c4];
        acc.x += p.x; acc.y += p.y; acc.z += p.z; acc.w += p.w;
    }
    ((float4*)y)[i] = acc;
}

// ---------------------------------------------------------------------------
extern "C" void kernel_launch(void* const* d_in, const int* in_sizes, int n_in,
                              void* d_out, int out_size) {
    const float* x   = (const float*)d_in[0];
    const float* Wg  = (const float*)d_in[1];
    const float* W1  = (const float*)d_in[2];
    const float* W2  = (const float*)d_in[3];
    const float* W3  = (const float*)d_in[4];
    const float* Ws1 = (const float*)d_in[5];
    const float* Ws2 = (const float*)d_in[6];
    const float* Ws3 = (const float*)d_in[7];
    float* y = (float*)d_out;

    cudaFuncSetAttribute(gemm_kernel<0>, cudaFuncAttributeMaxDynamicSharedMemorySize, GEMM_SMEM);
    cudaFuncSetAttribute(gemm_kernel<1>, cudaFuncAttributeMaxDynamicSharedMemorySize, GEMM_SMEM);
    cudaFuncSetAttribute(gemm_kernel<2>, cudaFuncAttributeMaxDynamicSharedMemorySize, GEMM_SMEM);
    cudaFuncSetAttribute(gemm_kernel<3>, cudaFuncAttributeMaxDynamicSharedMemorySize, GEMM_SMEM);

    zero_cnt_kernel<<<1, 32>>>();
    gate_kernel<<<TT, 128>>>(x, Wg);

    // routed gemm1 (x@W1, x@W3)
    gemm_kernel<0><<<dim3(HH / 64, CAP / 128, EE), 256, GEMM_SMEM>>>(
        x, nullptr, nullptr, W1, g_t1, DD, HH);
    gemm_kernel<0><<<dim3(HH / 64, CAP / 128, EE), 256, GEMM_SMEM>>>(
        x, nullptr, nullptr, W3, g_t3, DD, HH);
    // shared gemm1
    gemm_kernel<1><<<dim3(HS / 64, TT / 128, 1), 256, GEMM_SMEM>>>(
        x, nullptr, nullptr, Ws1, g_s1, DD, HS);
    gemm_kernel<1><<<dim3(HS / 64, TT / 128, 1), 256, GEMM_SMEM>>>(
        x, nullptr, nullptr, Ws3, g_s3, DD, HS);
    // activations -> bf16 hi/lo hidden
    act_kernel<<<(size_t)EE * CAP * HH / 1024, 256>>>(g_t1, g_t3, g_hhi, g_hlo);
    act_kernel<<<(size_t)TT * HS / 1024, 256>>>(g_s1, g_s3, g_shi, g_slo);
    // gemm2
    gemm_kernel<3><<<dim3(DD / 64, TT / 128, 1), 256, GEMM_SMEM>>>(
        nullptr, g_shi, g_slo, Ws2, y, HS, DD);
    gemm_kernel<2><<<dim3(DD / 64, CAP / 128, EE), 256, GEMM_SMEM>>>(
        nullptr, g_hhi, g_hlo, W2, nullptr, HH, DD);
    combine_kernel<<<(TT * DD) / 1024, 256>>>(y);
}